// round 12
// baseline (speedup 1.0000x reference)
#include <cuda_runtime.h>
#include <math.h>

// Problem constants (fixed: point_cloud [8, 4096, 3], K=20)
#define BATCH 8
#define NPTS  4096
#define KNN   20
#define TPB   512
#define WARPS (TPB / 32)          // 16 warps per CTA
#define CPB   55                  // CTAs per batch -> grid = 440 (one balanced wave @3/SM)
#define FULLM 0xFFFFFFFFu

__global__ __launch_bounds__(TPB, 3)
void knn_warp_kernel(const float* __restrict__ pc, float* __restrict__ out)
{
    // Whole batch staged as float4 (x, y, z, |p|^2): 64 KB dynamic smem.
    extern __shared__ float4 pts[];
    __shared__ int qctr;

    const int b   = blockIdx.x / CPB;
    const int cta = blockIdx.x % CPB;
    const float* __restrict__ pcb = pc + (size_t)b * NPTS * 3;

    if (threadIdx.x == 0) qctr = 0;
    for (int i = threadIdx.x; i < NPTS; i += TPB) {
        float x = pcb[3 * i + 0];
        float y = pcb[3 * i + 1];
        float z = pcb[3 * i + 2];
        pts[i] = make_float4(x, y, z, fmaf(x, x, fmaf(y, y, z * z)));
    }
    __syncthreads();

    const int lane = threadIdx.x & 31;

    // Query range for this CTA (74-75 queries), dynamically stolen by warps.
    const int qstart = (NPTS * cta) / CPB;
    const int qcount = (NPTS * (cta + 1)) / CPB - qstart;

    const long long BNK = (long long)BATCH * NPTS * KNN;
    float* __restrict__ srcA  = out;
    float* __restrict__ tgtA  = out + BNK;
    float* __restrict__ attA  = out + 2 * BNK;
    float* __restrict__ slocA = out + 3 * BNK;

    for (;;) {
        int t;
        if (lane == 0) t = atomicAdd(&qctr, 1);
        t = __shfl_sync(FULLM, t, 0);
        if (t >= qcount) break;
        const int qi = qstart + t;

        const float4 q = pts[qi];
        const float nx = -2.0f * q.x, ny = -2.0f * q.y, nz = -2.0f * q.z;
        const float sqq = q.w;

        // Ranking key r = |p|^2 - 2 q.p  (= d^2 - |q|^2): per-query constant
        // shift of d^2, so selection order and ties are identical; true d^2 is
        // restored in the epilogue. Lane-sorted list: lane l = (l+1)-th
        // smallest (r, idx). Exactness for lanes 0..21: the admission thr
        // (lane-21 snapshot) is conservative/stale; a candidate >= the current
        // lane-31 value yields an all-false pred in the drain and is dropped --
        // provably outside the exact top-22.
        float ld;
        int   li = lane;

        // ---- seed: exact bitonic sort of candidates 0..31 ----------------
        {
            float4 p = pts[lane];
            ld = fmaf(nx, p.x, fmaf(ny, p.y, fmaf(nz, p.z, p.w)));
        }
#pragma unroll
        for (int k = 2; k <= 32; k <<= 1) {
#pragma unroll
            for (int j = k >> 1; j > 0; j >>= 1) {
                float od = __shfl_xor_sync(FULLM, ld, j);
                int   oi = __shfl_xor_sync(FULLM, li, j);
                bool up     = (lane & k) == 0;       // ascending block
                bool iLower = (lane & j) == 0;       // lower index of the pair
                bool oless  = (od < ld) || ((od == ld) && (oi < li));
                bool take   = (iLower == up) ? oless : !oless;
                if (take) { ld = od; li = oi; }
            }
        }
        float thr = __shfl_sync(FULLM, ld, 21);

        // ---- half batch: candidates 32..63 -------------------------------
        {
            float4 p0 = pts[32 + lane];
            float d0 = fmaf(nx, p0.x, fmaf(ny, p0.y, fmaf(nz, p0.z, p0.w)));
            unsigned m0 = __ballot_sync(FULLM, d0 < thr);
            while (m0) {
                int srcl = __ffs(m0) - 1; m0 &= m0 - 1;
                float cd = __shfl_sync(FULLM, d0, srcl);
                int   cj = 32 + srcl;
                float ud = __shfl_up_sync(FULLM, ld, 1);
                int   ui = __shfl_up_sync(FULLM, li, 1);
                bool pred  = cd < ld;                 // strict: stable ties
                bool predp = (lane > 0) && (cd < ud);
                if (pred) {
                    ld = predp ? ud : cd;
                    li = predp ? ui : cj;
                }
            }
            thr = __shfl_sync(FULLM, ld, 21);
        }

        // ---- full batches: candidates 64..4095 ---------------------------
#pragma unroll 2
        for (int s = 0; s < (NPTS - 64) / 64; s++) {
            const int j0 = 64 + s * 64 + lane;
            float4 p0 = pts[j0];
            float4 p1 = pts[j0 + 32];
            float d0 = fmaf(nx, p0.x, fmaf(ny, p0.y, fmaf(nz, p0.z, p0.w)));
            float d1 = fmaf(nx, p1.x, fmaf(ny, p1.y, fmaf(nz, p1.z, p1.w)));

            unsigned m0 = __ballot_sync(FULLM, d0 < thr);
            unsigned m1 = __ballot_sync(FULLM, d1 < thr);

            if (m0 | m1) {
                // Drain ascending candidate index (top_k tie stability).
                while (m0) {
                    int srcl = __ffs(m0) - 1; m0 &= m0 - 1;
                    float cd = __shfl_sync(FULLM, d0, srcl);
                    int   cj = j0 - lane + srcl;
                    float ud = __shfl_up_sync(FULLM, ld, 1);
                    int   ui = __shfl_up_sync(FULLM, li, 1);
                    bool pred  = cd < ld;
                    bool predp = (lane > 0) && (cd < ud);
                    if (pred) {
                        ld = predp ? ud : cd;
                        li = predp ? ui : cj;
                    }
                }
                while (m1) {
                    int srcl = __ffs(m1) - 1; m1 &= m1 - 1;
                    float cd = __shfl_sync(FULLM, d1, srcl);
                    int   cj = j0 - lane + 32 + srcl;
                    float ud = __shfl_up_sync(FULLM, ld, 1);
                    int   ui = __shfl_up_sync(FULLM, li, 1);
                    bool pred  = cd < ld;
                    bool predp = (lane > 0) && (cd < ud);
                    if (pred) {
                        ld = predp ? ud : cd;
                        li = predp ? ui : cj;
                    }
                }
                thr = __shfl_sync(FULLM, ld, 21);     // refresh once per batch
            }
        }

        // ---- epilogue: lane 0 = self (r strictly minimal); lanes 1..20 ---
        const int row = b * NPTS + qi;
        float d2l = fmaxf(ld + sqq, 0.0f);            // back to true d^2
        float dk2 = __shfl_sync(FULLM, d2l, 20);      // k-th neighbor d^2
        float dk = sqrtf(dk2);
        float sigma = dk + 1e-6f;                     // BETA = 1
        float inv2s2 = 1.0f / (2.0f * sigma * sigma);

        const long long base = (long long)row * KNN;
        if (lane >= 1 && lane <= KNN) {
            int k = lane - 1;
            srcA[base + k] = (float)row;
            tgtA[base + k] = (float)(b * NPTS + li);
            attA[base + k] = expf(-d2l * inv2s2);
        }
        if (lane == 0) slocA[row] = dk * dk;          // LAMBDA = 1
    }
}

extern "C" void kernel_launch(void* const* d_in, const int* in_sizes, int n_in,
                              void* d_out, int out_size)
{
    (void)in_sizes; (void)n_in; (void)out_size;
    const float* pc = (const float*)d_in[0];
    float* outp = (float*)d_out;

    const size_t smem = (size_t)NPTS * sizeof(float4);   // 64 KB
    cudaFuncSetAttribute(knn_warp_kernel,
                         cudaFuncAttributeMaxDynamicSharedMemorySize, (int)smem);
    knn_warp_kernel<<<BATCH * CPB, TPB, smem>>>(pc, outp);
}

// round 13
// speedup vs baseline: 1.5421x; 1.5421x over previous
#include <cuda_runtime.h>
#include <math.h>

// Problem constants (fixed: point_cloud [8, 4096, 3], K=20)
#define BATCH 8
#define NPTS  4096
#define KNN   20
#define TPB   512
#define WARPS (TPB / 32)          // 16 warps per CTA
#define CPB   55                  // CTAs per batch -> grid = 440 (one balanced wave @3/SM)
#define FULLM 0xFFFFFFFFu

__global__ __launch_bounds__(TPB, 3)
void knn_warp_kernel(const float* __restrict__ pc, float* __restrict__ out)
{
    // Whole batch staged as float4 (x, y, z, |p|^2): 64 KB dynamic smem.
    extern __shared__ float4 pts[];
    __shared__ int qctr;

    const int b   = blockIdx.x / CPB;
    const int cta = blockIdx.x % CPB;
    const float* __restrict__ pcb = pc + (size_t)b * NPTS * 3;

    if (threadIdx.x == 0) qctr = 0;
    for (int i = threadIdx.x; i < NPTS; i += TPB) {
        float x = pcb[3 * i + 0];
        float y = pcb[3 * i + 1];
        float z = pcb[3 * i + 2];
        pts[i] = make_float4(x, y, z, fmaf(x, x, fmaf(y, y, z * z)));
    }
    __syncthreads();

    const int lane = threadIdx.x & 31;

    // Query range for this CTA (74-75 queries), dynamically stolen by warps.
    const int qstart = (NPTS * cta) / CPB;
    const int qcount = (NPTS * (cta + 1)) / CPB - qstart;

    const long long BNK = (long long)BATCH * NPTS * KNN;
    float* __restrict__ srcA = out;
    float* __restrict__ tgtA = out + BNK;
    float* __restrict__ attA = out + 2 * BNK;
    float* __restrict__ slocA = out + 3 * BNK;

    for (;;) {
        int t;
        if (lane == 0) t = atomicAdd(&qctr, 1);
        t = __shfl_sync(FULLM, t, 0);
        if (t >= qcount) break;
        const int qi = qstart + t;

        const float4 q = pts[qi];
        const float n2qx = -2.0f * q.x, n2qy = -2.0f * q.y, n2qz = -2.0f * q.z;
        const float sqq = q.w;

        // ---- seed: exact sort of the first 32 candidates ----------------
        // Lane-sorted list: lane l holds the (l+1)-th smallest (d2, idx),
        // lexicographic (d2, idx) -- identical semantics to stable insertion.
        float ld;
        int   li = lane;
        {
            float4 p = pts[lane];
            float tt = fmaf(n2qx, p.x, fmaf(n2qy, p.y, fmaf(n2qz, p.z, p.w)));
            ld = fmaxf(tt + sqq, 0.0f);
        }
#pragma unroll
        for (int k = 2; k <= 32; k <<= 1) {
#pragma unroll
            for (int j = k >> 1; j > 0; j >>= 1) {
                float od = __shfl_xor_sync(FULLM, ld, j);
                int   oi = __shfl_xor_sync(FULLM, li, j);
                bool up     = (lane & k) == 0;       // ascending block
                bool iLower = (lane & j) == 0;       // lower index of the pair
                bool oless  = (od < ld) || ((od == ld) && (oi < li));
                bool take   = (iLower == up) ? oless : !oless;
                if (take) { ld = od; li = oi; }
            }
        }
        float thr = __shfl_sync(FULLM, ld, 21);

        // ---- half batch: candidates 32..63 -------------------------------
        {
            float4 p0 = pts[32 + lane];
            float t0 = fmaf(n2qx, p0.x, fmaf(n2qy, p0.y, fmaf(n2qz, p0.z, p0.w)));
            float d0 = fmaxf(t0 + sqq, 0.0f);
            unsigned m0 = __ballot_sync(FULLM, d0 < thr);
            while (m0) {
                int srcl = __ffs(m0) - 1; m0 &= m0 - 1;
                float cd = __shfl_sync(FULLM, d0, srcl);
                int   cj = 32 + srcl;
                float ud = __shfl_up_sync(FULLM, ld, 1);
                int   ui = __shfl_up_sync(FULLM, li, 1);
                bool pred  = cd < ld;                 // strict: stable ties
                bool predp = (lane > 0) && (cd < ud);
                if (pred) {
                    ld = predp ? ud : cd;
                    li = predp ? ui : cj;
                }
            }
            thr = __shfl_sync(FULLM, ld, 21);
        }

        // ---- full batches: candidates 64..4095 ---------------------------
        // Admission thr (lane-21 snapshot) is conservative/stale; a candidate
        // >= current lane-31 value yields all-false pred and is dropped --
        // provably outside the exact top-22, so lanes 0..21 stay exact.
#pragma unroll 2
        for (int s = 0; s < (NPTS - 64) / 64; s++) {
            const int j0 = 64 + s * 64 + lane;
            float4 p0 = pts[j0];
            float4 p1 = pts[j0 + 32];
            float t0 = fmaf(n2qx, p0.x, fmaf(n2qy, p0.y, fmaf(n2qz, p0.z, p0.w)));
            float t1 = fmaf(n2qx, p1.x, fmaf(n2qy, p1.y, fmaf(n2qz, p1.z, p1.w)));
            float d0 = fmaxf(t0 + sqq, 0.0f);
            float d1 = fmaxf(t1 + sqq, 0.0f);

            unsigned m0 = __ballot_sync(FULLM, d0 < thr);
            unsigned m1 = __ballot_sync(FULLM, d1 < thr);

            if (m0 | m1) {
                // Drain ascending candidate index (top_k tie stability).
                while (m0) {
                    int srcl = __ffs(m0) - 1; m0 &= m0 - 1;
                    float cd = __shfl_sync(FULLM, d0, srcl);
                    int   cj = j0 - lane + srcl;
                    float ud = __shfl_up_sync(FULLM, ld, 1);
                    int   ui = __shfl_up_sync(FULLM, li, 1);
                    bool pred  = cd < ld;
                    bool predp = (lane > 0) && (cd < ud);
                    if (pred) {
                        ld = predp ? ud : cd;
                        li = predp ? ui : cj;
                    }
                }
                while (m1) {
                    int srcl = __ffs(m1) - 1; m1 &= m1 - 1;
                    float cd = __shfl_sync(FULLM, d1, srcl);
                    int   cj = j0 - lane + 32 + srcl;
                    float ud = __shfl_up_sync(FULLM, ld, 1);
                    int   ui = __shfl_up_sync(FULLM, li, 1);
                    bool pred  = cd < ld;
                    bool predp = (lane > 0) && (cd < ud);
                    if (pred) {
                        ld = predp ? ud : cd;
                        li = predp ? ui : cj;
                    }
                }
                thr = __shfl_sync(FULLM, ld, 21);     // refresh once per batch
            }
        }

        // Lane 0 = self (d2 ~ 0, strict minimum); neighbors = lanes 1..20.
        const int row = b * NPTS + qi;
        float dk2 = __shfl_sync(FULLM, ld, 20);       // k-th neighbor d2
        float dk = sqrtf(dk2);
        float sigma = dk + 1e-6f;                     // BETA = 1
        float inv2s2 = 1.0f / (2.0f * sigma * sigma);

        const long long base = (long long)row * KNN;
        if (lane >= 1 && lane <= KNN) {
            int k = lane - 1;
            srcA[base + k] = (float)row;
            tgtA[base + k] = (float)(b * NPTS + li);
            attA[base + k] = __expf(-ld * inv2s2);
        }
        if (lane == 0) slocA[row] = dk * dk;          // LAMBDA = 1
    }
}

extern "C" void kernel_launch(void* const* d_in, const int* in_sizes, int n_in,
                              void* d_out, int out_size)
{
    (void)in_sizes; (void)n_in; (void)out_size;
    const float* pc = (const float*)d_in[0];
    float* outp = (float*)d_out;

    const size_t smem = (size_t)NPTS * sizeof(float4);   // 64 KB
    cudaFuncSetAttribute(knn_warp_kernel,
                         cudaFuncAttributeMaxDynamicSharedMemorySize, (int)smem);
    knn_warp_kernel<<<BATCH * CPB, TPB, smem>>>(pc, outp);
}

// round 15
// speedup vs baseline: 1.5875x; 1.0294x over previous
#include <cuda_runtime.h>
#include <math.h>

// Problem constants (fixed: point_cloud [8, 4096, 3], K=20)
#define BATCH 8
#define NPTS  4096
#define KNN   20
#define TPB   512
#define WARPS (TPB / 32)          // 16 warps per CTA
#define CPB   55                  // CTAs per batch -> grid = 440 (one balanced wave @3/SM)
#define FULLM 0xFFFFFFFFu

__global__ __launch_bounds__(TPB, 3)
void knn_warp_kernel(const float* __restrict__ pc, float* __restrict__ out)
{
    // Whole batch staged as float4 (x, y, z, |p|^2): 64 KB dynamic smem.
    extern __shared__ float4 pts[];
    __shared__ int qctr;

    const int b   = blockIdx.x / CPB;
    const int cta = blockIdx.x % CPB;
    const float* __restrict__ pcb = pc + (size_t)b * NPTS * 3;

    if (threadIdx.x == 0) qctr = 0;
    for (int i = threadIdx.x; i < NPTS; i += TPB) {
        float x = pcb[3 * i + 0];
        float y = pcb[3 * i + 1];
        float z = pcb[3 * i + 2];
        pts[i] = make_float4(x, y, z, fmaf(x, x, fmaf(y, y, z * z)));
    }
    __syncthreads();

    const int lane = threadIdx.x & 31;

    // Query range for this CTA (74-75 queries), dynamically stolen by warps.
    const int qstart = (NPTS * cta) / CPB;
    const int qcount = (NPTS * (cta + 1)) / CPB - qstart;

    const long long BNK = (long long)BATCH * NPTS * KNN;
    float* __restrict__ srcA = out;
    float* __restrict__ tgtA = out + BNK;
    float* __restrict__ attA = out + 2 * BNK;
    float* __restrict__ slocA = out + 3 * BNK;

    for (;;) {
        int t;
        if (lane == 0) t = atomicAdd(&qctr, 1);
        t = __shfl_sync(FULLM, t, 0);
        if (t >= qcount) break;
        const int qi = qstart + t;

        const float4 q = pts[qi];
        const float n2qx = -2.0f * q.x, n2qy = -2.0f * q.y, n2qz = -2.0f * q.z;
        const float sqq = q.w;

        // ---- seed: exact sort of the first 64 candidates, keep lowest 32 --
        // Two lane-sorted 32-lists built in parallel (dual bitonic), then the
        // lowest-32-of-64 via reverse-compare + bitonic clean. Lexicographic
        // (d2, idx) everywhere -- identical semantics to stable insertion.
        float ld, ld1;
        int   li = lane, li1 = 32 + lane;
        {
            float4 p0 = pts[lane];
            float4 p1 = pts[32 + lane];
            float t0 = fmaf(n2qx, p0.x, fmaf(n2qy, p0.y, fmaf(n2qz, p0.z, p0.w)));
            float t1 = fmaf(n2qx, p1.x, fmaf(n2qy, p1.y, fmaf(n2qz, p1.z, p1.w)));
            ld  = fmaxf(t0 + sqq, 0.0f);
            ld1 = fmaxf(t1 + sqq, 0.0f);
        }
#pragma unroll
        for (int k = 2; k <= 32; k <<= 1) {
#pragma unroll
            for (int j = k >> 1; j > 0; j >>= 1) {
                bool up     = (lane & k) == 0;       // ascending block
                bool iLower = (lane & j) == 0;       // lower index of the pair
                float od  = __shfl_xor_sync(FULLM, ld,  j);
                int   oi  = __shfl_xor_sync(FULLM, li,  j);
                float od1 = __shfl_xor_sync(FULLM, ld1, j);
                int   oi1 = __shfl_xor_sync(FULLM, li1, j);
                bool oless  = (od  < ld ) || ((od  == ld ) && (oi  < li ));
                bool oless1 = (od1 < ld1) || ((od1 == ld1) && (oi1 < li1));
                bool take   = (iLower == up) ? oless  : !oless;
                bool take1  = (iLower == up) ? oless1 : !oless1;
                if (take)  { ld  = od;  li  = oi;  }
                if (take1) { ld1 = od1; li1 = oi1; }
            }
        }
        // lowest-32 of 64: min(A[lane], B[31-lane]) -> bitonic, then clean.
        {
            float md = __shfl_sync(FULLM, ld1, 31 - lane);
            int   mi = __shfl_sync(FULLM, li1, 31 - lane);
            bool mless = (md < ld) || ((md == ld) && (mi < li));
            if (mless) { ld = md; li = mi; }
#pragma unroll
            for (int j = 16; j > 0; j >>= 1) {
                float od = __shfl_xor_sync(FULLM, ld, j);
                int   oi = __shfl_xor_sync(FULLM, li, j);
                bool iLower = (lane & j) == 0;
                bool oless  = (od < ld) || ((od == ld) && (oi < li));
                bool take   = iLower ? oless : !oless;
                if (take) { ld = od; li = oi; }
            }
        }
        float thr = __shfl_sync(FULLM, ld, 20);

        // ---- full batches: candidates 64..4095 ---------------------------
        // Admission thr (lane-20 snapshot) is exact-for-top-21 though stale:
        // a rejected candidate had 21 earlier-indexed elements with d2 <= its
        // own, all of which precede it under top_k's index-stable tie-break.
        // In the drain, a candidate >= the current lane-31 value yields an
        // all-false pred and is dropped -- outside the top-21 a fortiori.
#pragma unroll 2
        for (int s = 0; s < (NPTS - 64) / 64; s++) {
            const int j0 = 64 + s * 64 + lane;
            float4 p0 = pts[j0];
            float4 p1 = pts[j0 + 32];
            float t0 = fmaf(n2qx, p0.x, fmaf(n2qy, p0.y, fmaf(n2qz, p0.z, p0.w)));
            float t1 = fmaf(n2qx, p1.x, fmaf(n2qy, p1.y, fmaf(n2qz, p1.z, p1.w)));
            float d0 = fmaxf(t0 + sqq, 0.0f);
            float d1 = fmaxf(t1 + sqq, 0.0f);

            unsigned m0 = __ballot_sync(FULLM, d0 < thr);
            unsigned m1 = __ballot_sync(FULLM, d1 < thr);

            if (m0 | m1) {
                // Drain ascending candidate index (top_k tie stability).
                while (m0) {
                    int srcl = __ffs(m0) - 1; m0 &= m0 - 1;
                    float cd = __shfl_sync(FULLM, d0, srcl);
                    int   cj = j0 - lane + srcl;
                    float ud = __shfl_up_sync(FULLM, ld, 1);
                    int   ui = __shfl_up_sync(FULLM, li, 1);
                    bool pred  = cd < ld;                 // strict: stable ties
                    bool predp = (lane > 0) && (cd < ud);
                    if (pred) {
                        ld = predp ? ud : cd;
                        li = predp ? ui : cj;
                    }
                }
                while (m1) {
                    int srcl = __ffs(m1) - 1; m1 &= m1 - 1;
                    float cd = __shfl_sync(FULLM, d1, srcl);
                    int   cj = j0 - lane + 32 + srcl;
                    float ud = __shfl_up_sync(FULLM, ld, 1);
                    int   ui = __shfl_up_sync(FULLM, li, 1);
                    bool pred  = cd < ld;
                    bool predp = (lane > 0) && (cd < ud);
                    if (pred) {
                        ld = predp ? ud : cd;
                        li = predp ? ui : cj;
                    }
                }
                thr = __shfl_sync(FULLM, ld, 20);     // refresh once per batch
            }
        }

        // Lane 0 = self (d2 ~ 0, strict minimum); neighbors = lanes 1..20.
        const int row = b * NPTS + qi;
        float dk2 = __shfl_sync(FULLM, ld, 20);       // k-th neighbor d2
        float dk = sqrtf(dk2);
        float sigma = dk + 1e-6f;                     // BETA = 1
        float inv2s2 = 1.0f / (2.0f * sigma * sigma);

        const long long base = (long long)row * KNN;
        if (lane >= 1 && lane <= KNN) {
            int k = lane - 1;
            srcA[base + k] = (float)row;
            tgtA[base + k] = (float)(b * NPTS + li);
            attA[base + k] = __expf(-ld * inv2s2);
        }
        if (lane == 0) slocA[row] = dk * dk;          // LAMBDA = 1
    }
}

extern "C" void kernel_launch(void* const* d_in, const int* in_sizes, int n_in,
                              void* d_out, int out_size)
{
    (void)in_sizes; (void)n_in; (void)out_size;
    const float* pc = (const float*)d_in[0];
    float* outp = (float*)d_out;

    const size_t smem = (size_t)NPTS * sizeof(float4);   // 64 KB
    cudaFuncSetAttribute(knn_warp_kernel,
                         cudaFuncAttributeMaxDynamicSharedMemorySize, (int)smem);
    knn_warp_kernel<<<BATCH * CPB, TPB, smem>>>(pc, outp);
}

// round 16
// speedup vs baseline: 1.5980x; 1.0066x over previous
#include <cuda_runtime.h>
#include <math.h>

// Problem constants (fixed: point_cloud [8, 4096, 3], K=20)
#define BATCH 8
#define NPTS  4096
#define KNN   20
#define TPB   512
#define WARPS (TPB / 32)          // 16 warps per CTA
#define CPB   55                  // CTAs per batch -> grid = 440 (one balanced wave @3/SM)
#define FULLM 0xFFFFFFFFu

__global__ __launch_bounds__(TPB, 3)
void knn_warp_kernel(const float* __restrict__ pc, float* __restrict__ out)
{
    // Whole batch staged as float4 (x, y, z, |p|^2): 64 KB dynamic smem.
    extern __shared__ float4 pts[];
    __shared__ int qctr;

    const int b   = blockIdx.x / CPB;
    const int cta = blockIdx.x % CPB;
    const float* __restrict__ pcb = pc + (size_t)b * NPTS * 3;

    if (threadIdx.x == 0) qctr = 0;
    for (int i = threadIdx.x; i < NPTS; i += TPB) {
        float x = pcb[3 * i + 0];
        float y = pcb[3 * i + 1];
        float z = pcb[3 * i + 2];
        pts[i] = make_float4(x, y, z, fmaf(x, x, fmaf(y, y, z * z)));
    }
    __syncthreads();

    const int lane = threadIdx.x & 31;

    // Query range for this CTA (74-75 queries), dynamically stolen by warps.
    const int qstart = (NPTS * cta) / CPB;
    const int qcount = (NPTS * (cta + 1)) / CPB - qstart;

    const long long BNK = (long long)BATCH * NPTS * KNN;
    float* __restrict__ srcA = out;
    float* __restrict__ tgtA = out + BNK;
    float* __restrict__ attA = out + 2 * BNK;
    float* __restrict__ slocA = out + 3 * BNK;

    for (;;) {
        int t;
        if (lane == 0) t = atomicAdd(&qctr, 1);
        t = __shfl_sync(FULLM, t, 0);
        if (t >= qcount) break;
        const int qi = qstart + t;

        const float4 q = pts[qi];
        const float n2qx = -2.0f * q.x, n2qy = -2.0f * q.y, n2qz = -2.0f * q.z;
        const float sqq = q.w;

        // ---- seed: exact sort of the first 64 candidates, keep lowest 32 --
        // Two lane-sorted 32-lists built in parallel (dual bitonic), then the
        // lowest-32-of-64 via reverse-compare + bitonic clean. Lexicographic
        // (d2, idx) everywhere -- identical semantics to stable insertion.
        float ld, ld1;
        int   li = lane, li1 = 32 + lane;
        {
            float4 p0 = pts[lane];
            float4 p1 = pts[32 + lane];
            float t0 = fmaf(n2qx, p0.x, fmaf(n2qy, p0.y, fmaf(n2qz, p0.z, p0.w)));
            float t1 = fmaf(n2qx, p1.x, fmaf(n2qy, p1.y, fmaf(n2qz, p1.z, p1.w)));
            ld  = fmaxf(t0 + sqq, 0.0f);
            ld1 = fmaxf(t1 + sqq, 0.0f);
        }
#pragma unroll
        for (int k = 2; k <= 32; k <<= 1) {
#pragma unroll
            for (int j = k >> 1; j > 0; j >>= 1) {
                bool up     = (lane & k) == 0;       // ascending block
                bool iLower = (lane & j) == 0;       // lower index of the pair
                float od  = __shfl_xor_sync(FULLM, ld,  j);
                int   oi  = __shfl_xor_sync(FULLM, li,  j);
                float od1 = __shfl_xor_sync(FULLM, ld1, j);
                int   oi1 = __shfl_xor_sync(FULLM, li1, j);
                bool oless  = (od  < ld ) || ((od  == ld ) && (oi  < li ));
                bool oless1 = (od1 < ld1) || ((od1 == ld1) && (oi1 < li1));
                bool take   = (iLower == up) ? oless  : !oless;
                bool take1  = (iLower == up) ? oless1 : !oless1;
                if (take)  { ld  = od;  li  = oi;  }
                if (take1) { ld1 = od1; li1 = oi1; }
            }
        }
        // lowest-32 of 64: min(A[lane], B[31-lane]) -> bitonic, then clean.
        {
            float md = __shfl_sync(FULLM, ld1, 31 - lane);
            int   mi = __shfl_sync(FULLM, li1, 31 - lane);
            bool mless = (md < ld) || ((md == ld) && (mi < li));
            if (mless) { ld = md; li = mi; }
#pragma unroll
            for (int j = 16; j > 0; j >>= 1) {
                float od = __shfl_xor_sync(FULLM, ld, j);
                int   oi = __shfl_xor_sync(FULLM, li, j);
                bool iLower = (lane & j) == 0;
                bool oless  = (od < ld) || ((od == ld) && (oi < li));
                bool take   = iLower ? oless : !oless;
                if (take) { ld = od; li = oi; }
            }
        }
        float thr = __shfl_sync(FULLM, ld, 20);

        // ---- full batches: candidates 64..4095 ---------------------------
        // Admission thr (lane-20 snapshot) is exact-for-top-21 though stale:
        // a rejected candidate had 21 earlier-indexed elements with d2 <= its
        // own, all of which precede it under top_k's index-stable tie-break.
        // In the drain, a candidate >= the current lane-31 value yields an
        // all-false pred and is dropped -- outside the top-21 a fortiori.
#pragma unroll 4
        for (int s = 0; s < (NPTS - 64) / 64; s++) {
            const int j0 = 64 + s * 64 + lane;
            float4 p0 = pts[j0];
            float4 p1 = pts[j0 + 32];
            float t0 = fmaf(n2qx, p0.x, fmaf(n2qy, p0.y, fmaf(n2qz, p0.z, p0.w)));
            float t1 = fmaf(n2qx, p1.x, fmaf(n2qy, p1.y, fmaf(n2qz, p1.z, p1.w)));
            float d0 = fmaxf(t0 + sqq, 0.0f);
            float d1 = fmaxf(t1 + sqq, 0.0f);

            unsigned m0 = __ballot_sync(FULLM, d0 < thr);
            unsigned m1 = __ballot_sync(FULLM, d1 < thr);

            if (m0 | m1) {
                // Drain ascending candidate index (top_k tie stability).
                while (m0) {
                    int srcl = __ffs(m0) - 1; m0 &= m0 - 1;
                    float cd = __shfl_sync(FULLM, d0, srcl);
                    int   cj = j0 - lane + srcl;
                    float ud = __shfl_up_sync(FULLM, ld, 1);
                    int   ui = __shfl_up_sync(FULLM, li, 1);
                    bool pred  = cd < ld;                 // strict: stable ties
                    bool predp = (lane > 0) && (cd < ud);
                    if (pred) {
                        ld = predp ? ud : cd;
                        li = predp ? ui : cj;
                    }
                }
                while (m1) {
                    int srcl = __ffs(m1) - 1; m1 &= m1 - 1;
                    float cd = __shfl_sync(FULLM, d1, srcl);
                    int   cj = j0 - lane + 32 + srcl;
                    float ud = __shfl_up_sync(FULLM, ld, 1);
                    int   ui = __shfl_up_sync(FULLM, li, 1);
                    bool pred  = cd < ld;
                    bool predp = (lane > 0) && (cd < ud);
                    if (pred) {
                        ld = predp ? ud : cd;
                        li = predp ? ui : cj;
                    }
                }
                thr = __shfl_sync(FULLM, ld, 20);     // refresh once per batch
            }
        }

        // Lane 0 = self (d2 ~ 0, strict minimum); neighbors = lanes 1..20.
        const int row = b * NPTS + qi;
        float dk2 = __shfl_sync(FULLM, ld, 20);       // k-th neighbor d2
        float dk = sqrtf(dk2);
        float sigma = dk + 1e-6f;                     // BETA = 1
        float inv2s2 = 1.0f / (2.0f * sigma * sigma);

        const long long base = (long long)row * KNN;
        if (lane >= 1 && lane <= KNN) {
            int k = lane - 1;
            srcA[base + k] = (float)row;
            tgtA[base + k] = (float)(b * NPTS + li);
            attA[base + k] = __expf(-ld * inv2s2);
        }
        if (lane == 0) slocA[row] = dk * dk;          // LAMBDA = 1
    }
}

extern "C" void kernel_launch(void* const* d_in, const int* in_sizes, int n_in,
                              void* d_out, int out_size)
{
    (void)in_sizes; (void)n_in; (void)out_size;
    const float* pc = (const float*)d_in[0];
    float* outp = (float*)d_out;

    const size_t smem = (size_t)NPTS * sizeof(float4);   // 64 KB
    cudaFuncSetAttribute(knn_warp_kernel,
                         cudaFuncAttributeMaxDynamicSharedMemorySize, (int)smem);
    knn_warp_kernel<<<BATCH * CPB, TPB, smem>>>(pc, outp);
}